// round 15
// baseline (speedup 1.0000x reference)
#include <cuda_runtime.h>
#include <cstdint>

// ---- problem constants (match reference) ----
#define BB 4
#define HH 128
#define WW 128
#define SS 72
#define SPS 24          // slices per stack
#define ZS 120          // z_scale
#define ZV 122          // padded depth
#define ST_RATIO 5.0f

#define VOXELS (BB * HH * WW * ZV)      // 7,995,392
#define PIXELS (BB * HH * WW * SS)      // 4,718,592
#define OUT_PER (BB * HH * WW * ZS)     // 7,864,320
#define HWSZ   (HH * WW)                // 16384

#define CHAIN 16                         // pixels per thread along the chain axis

// Interleaved scratch: [2*lin]=N, [2*lin+1]=D. 64 MB, L2-resident.
// Tail cudaMemsetAsync restores the all-zero invariant after every execution.
__device__ __align__(16) float g_acc[2 * VOXELS];

__device__ __forceinline__ void red_add_v2(float* p, float a, float b) {
    asm volatile("red.global.add.v2.f32 [%0], {%1, %2};"
                 :: "l"(p), "f"(a), "f"(b) : "memory");
}

__device__ __forceinline__ void red_add_v4(float* p, float a, float b,
                                           float c, float d) {
    asm volatile("red.global.add.v4.f32 [%0], {%1, %2, %3, %4};"
                 :: "l"(p), "f"(a), "f"(b), "f"(c), "f"(d) : "memory");
}

// Per-axis corner terms: clipped address contributions + masked weights.
struct Axis { int t0, t1; float f0, f1; };

__device__ __forceinline__ Axis axis_eval(float q, int E, int St) {
    float qf = floorf(q);
    int q0 = (int)qf;
    float fr = q - qf;
    int i0 = min(max(q0, 0), E - 1);
    int i1 = min(max(q0 + 1, 0), E - 1);
    Axis a;
    a.t0 = i0 * St;
    a.t1 = i1 * St;
    a.f0 = (q0 >= 0 && q0 < E)      ? (1.0f - fr) : 0.0f;
    a.f1 = (q0 >= -1 && q0 < E - 1) ? fr          : 0.0f;
    return a;
}

// ---------------------------------------------------------------------------
// Splat. Orientation is BLOCK-uniform (8 warps = 8 slices of one stack).
// Axis roles (V = lane-merge axis, U = serial-chain axis, C = 2 free corners):
//   axi (o=0): lanes span w, chain along h.  V=y(ZV)      U=x(W*ZV)  C=z(1)
//   cor (o=1): lanes span h, chain along w.  V=x(W*ZV)    U=z(1)     C=y(ZV)
//   sag (o=2): lanes span h, chain along w.  V=y(ZV)      U=z(1)     C=x(W*ZV)
// Lane merge: lane l's V-hi absorbed by lane l+1's V-lo on exact address match.
// Chain merge: pixel p's U-hi row carried in registers, absorbed by p+1's U-lo.
// Red vectorization (v4 costs one v2; only lane-uniform fusion pays):
//   axi: the two C-corners are z-adjacent -> per-pixel v4 fusion.
//   cor/sag: U=z stride 1 -> consecutive chain steps emit ADJACENT addresses;
//   a 1-deep pending buffer pairs them into one v4 per two steps.
// Grid = B * 9(sc) * 8 * 4 = 1152 blocks of 256.
// ---------------------------------------------------------------------------
__global__ __launch_bounds__(256) void splat_kernel(
    const float* __restrict__ vol,    // (B,H,W,S,1)
    const float* __restrict__ trf)    // (B,S,3,4)
{
    __shared__ float sv[CHAIN * 32 * 9];  // [ (row*32 + lane)*9 + s_local ]

    int tid  = threadIdx.x;
    int lane = tid & 31;
    int wid  = tid >> 5;
    int blk  = blockIdx.x;

    int wc = blk & 3;
    int tt = blk >> 2;
    int hc = tt & 7;   tt >>= 3;
    int sc = tt % 9;
    int b  = tt / 9;

    int o = sc / 3;                   // block-uniform orientation
    int s = sc * 8 + wid;             // warp-uniform slice

    // Pixel footprint per orientation:
    //   axi:     h in [h0, h0+CHAIN) (chain), w in [w0, w0+32) (lanes)
    //   cor/sag: h in [h0, h0+32) (lanes),   w in [w0, w0+CHAIN) (chain)
    int h0, w0;
    if (o == 0) { h0 = hc * CHAIN; w0 = wc * 32; }
    else        { h0 = wc * 32;    w0 = hc * CHAIN; }

    // Stage the block's vol tile: tile row = chain index, tile col = lane.
    // Each warp reads 4 (h,w) sites x 8 contiguous s floats = 4 full sectors.
    {
        #pragma unroll
        for (int it = 0; it < CHAIN; it++) {
            int idx = it * 256 + tid;
            int row = idx >> 8;
            int ln  = (idx >> 3) & 31;
            int sl  = idx & 7;
            int hh = (o == 0) ? h0 + row : h0 + ln;
            int ww = (o == 0) ? w0 + ln  : w0 + row;
            sv[(row * 32 + ln) * 9 + sl] =
                vol[((size_t)(b * HH + hh) * WW + ww) * SS + sc * 8 + sl];
        }
    }
    __syncthreads();

    const float* Ap = trf + (size_t)(b * SS + s) * 12;
    float A00 = Ap[0] + 1.0f, A01 = Ap[1],        A02 = Ap[2],         A03 = Ap[3];
    float A10 = Ap[4],        A11 = Ap[5] + 1.0f, A12 = Ap[6],         A13 = Ap[7];
    float A20 = Ap[8],        A21 = Ap[9],        A22 = Ap[10] + 1.0f, A23 = Ap[11];

    float tc = (float)(s % SPS) * ST_RATIO;
    int bb = b * HH * WW * ZV;

    // chain carry per c-corner: pixel p's U-hi row awaiting merge with p+1
    int   cLoA[2] = { -1, -1 };
    float cLoN[2], cLoD[2];
    int   cHiA[2];
    float cHiN[2], cHiD[2];
    bool  cHiS[2] = { false, false };

    // pending lo emission per c-corner (cor/sag chain-pair v4 fusion)
    int   pA[2] = { -1, -1 };
    float pN[2], pD[2];

    for (int p = 0; p < CHAIN; p++) {
        float v = sv[(p * 32 + lane) * 9 + wid];       // conflict-free
        float nbV = __shfl_up_sync(0xffffffffu, v, 1); // neighbor intensity

        float fh = (o == 0) ? (float)(h0 + p)    : (float)(h0 + lane);
        float fw = (o == 0) ? (float)(w0 + lane) : (float)(w0 + p);

        float bx, by, bz;
        if (o == 0)      { bx = fh; by = fw; bz = tc; }
        else if (o == 1) { bx = fh; by = tc; bz = fw; }
        else             { bx = tc; by = fh; bz = fw; }

        float x = A00 * bx + A01 * by + A02 * bz + A03;
        float y = A10 * bx + A11 * by + A12 * bz + A13;
        float z = A20 * bx + A21 * by + A22 * bz + A23 + 1.0f;

        Axis U, V, C;
        if (o == 0) {
            U = axis_eval(x, HH, WW * ZV);   // chain axis
            V = axis_eval(y, WW, ZV);        // lane axis
            C = axis_eval(z, ZV, 1);
        } else if (o == 1) {
            V = axis_eval(x, HH, WW * ZV);   // lane axis
            U = axis_eval(z, ZV, 1);         // chain axis
            C = axis_eval(y, WW, ZV);
        } else {
            V = axis_eval(y, WW, ZV);        // lane axis
            U = axis_eval(z, ZV, 1);         // chain axis
            C = axis_eval(x, HH, WW * ZV);
        }

        int   eL[2];
        float eN[2], eD[2];

        #pragma unroll
        for (int c = 0; c < 2; c++) {
            int   ct = c ? C.t1 : C.t0;
            float fc = c ? C.f1 : C.f0;

            int   rL[2], rH[2];
            float rAccN[2], rAccD[2], rHiN[2], rHiD[2];
            bool  rS[2];

            // lane merge (V axis), for both chain rows (U lo/hi)
            #pragma unroll
            for (int r = 0; r < 2; r++) {
                int   ut = r ? U.t1 : U.t0;
                float fu = r ? U.f1 : U.f0;
                int L  = bb + ut + V.t0 + ct;
                int Hh = bb + ut + V.t1 + ct;
                float wlo = fu * V.f0 * fc;
                float whi = fu * V.f1 * fc;
                float NhiV = whi * v;

                float nbD = __shfl_up_sync(0xffffffffu, whi, 1);
                int   nbH = __shfl_up_sync(0xffffffffu, Hh, 1);
                float nbN = nbD * nbV;
                bool mrg = (lane > 0) && (nbH == L);
                unsigned bal = __ballot_sync(0xffffffffu, mrg);
                bool absorbed = (bal & (2u << lane)) != 0u;  // lane31 -> false

                rL[r]    = L;
                rAccN[r] = wlo * v + (mrg ? nbN : 0.0f);
                rAccD[r] = wlo     + (mrg ? nbD : 0.0f);
                rH[r]    = Hh;
                rHiN[r]  = NhiV;
                rHiD[r]  = whi;
                rS[r]    = !absorbed;
            }

            // chain merge: absorb previous pixel's U-hi row into this U-lo row
            if (cLoA[c] >= 0) {
                if (cLoA[c] == rL[0]) {
                    rAccN[0] += cLoN[c];
                    rAccD[0] += cLoD[c];
                } else {
                    red_add_v2(&g_acc[2 * cLoA[c]], cLoN[c], cLoD[c]);
                }
                if (cHiS[c]) {
                    if (rS[0] && cHiA[c] == rH[0]) {
                        rHiN[0] += cHiN[c];
                        rHiD[0] += cHiD[c];
                    } else {
                        red_add_v2(&g_acc[2 * cHiA[c]], cHiN[c], cHiD[c]);
                    }
                }
            }

            // record U-lo emission; emit surviving U-lo V-hi now (rare)
            eL[c] = rL[0]; eN[c] = rAccN[0]; eD[c] = rAccD[0];
            if (rS[0])
                red_add_v2(&g_acc[2 * rH[0]], rHiN[0], rHiD[0]);

            // U-hi row becomes the new chain carry
            cLoA[c] = rL[1]; cLoN[c] = rAccN[1]; cLoD[c] = rAccD[1];
            cHiA[c] = rH[1]; cHiN[c] = rHiN[1]; cHiD[c] = rHiD[1];
            cHiS[c] = rS[1];
        }

        // ---- emit the two lo-rows ----
        if (o == 0) {
            // axi: the two C-corners are z-adjacent -> per-pixel v4 fusion
            bool fuse = (eL[1] == eL[0] + 1) && ((eL[0] & 1) == 0);
            if (fuse) {
                red_add_v4(&g_acc[2 * eL[0]], eN[0], eD[0], eN[1], eD[1]);
            } else {
                red_add_v2(&g_acc[2 * eL[0]], eN[0], eD[0]);
                red_add_v2(&g_acc[2 * eL[1]], eN[1], eD[1]);
            }
        } else {
            // cor/sag: chain steps emit consecutive addresses (U=z stride 1);
            // pair them via a 1-deep pending buffer into one v4 per two steps.
            #pragma unroll
            for (int c = 0; c < 2; c++) {
                if (pA[c] >= 0) {
                    if (((pA[c] & 1) == 0) && (eL[c] == pA[c] + 1)) {
                        red_add_v4(&g_acc[2 * pA[c]], pN[c], pD[c], eN[c], eD[c]);
                        pA[c] = -1;
                        continue;
                    }
                    red_add_v2(&g_acc[2 * pA[c]], pN[c], pD[c]);
                }
                pA[c] = eL[c]; pN[c] = eN[c]; pD[c] = eD[c];
            }
        }
    }

    // flush pending lo emissions and remaining chain carries
    #pragma unroll
    for (int c = 0; c < 2; c++) {
        if (pA[c] >= 0)
            red_add_v2(&g_acc[2 * pA[c]], pN[c], pD[c]);
        if (cLoA[c] >= 0) {
            red_add_v2(&g_acc[2 * cLoA[c]], cLoN[c], cLoD[c]);
            if (cHiS[c])
                red_add_v2(&g_acc[2 * cHiA[c]], cHiN[c], cHiD[c]);
        }
    }
}

// ---------------------------------------------------------------------------
// Finalize (R11 version — measured best): crop z[1:1+ZS], split N/D,
// where(D<=0, 1, D). One warp per (b,h,w) column, strided passes of 32 z
// (last predicated). __ldcs on acc (dead after read), __stcs on out.
// Grid = HWSZ*BB/8 = 8192 blocks of 256 (8 warps = 8 columns per block).
// ---------------------------------------------------------------------------
__global__ __launch_bounds__(256) void finalize_kernel(float* __restrict__ out)
{
    int lane = threadIdx.x & 31;
    int col  = blockIdx.x * 8 + (threadIdx.x >> 5);   // global hwb column

    const float2* acc = reinterpret_cast<const float2*>(g_acc);
    int lin = col * ZV + 1;
    int oj  = col * ZS;

    float2 p0 = __ldcs(&acc[lin + lane]);
    float2 p1 = __ldcs(&acc[lin + lane + 32]);
    float2 p2 = __ldcs(&acc[lin + lane + 64]);
    float2 p3 = (lane < 24) ? __ldcs(&acc[lin + lane + 96]) : make_float2(0.f, 0.f);

    __stcs(&out[oj + lane],      p0.x);
    __stcs(&out[oj + lane + 32], p1.x);
    __stcs(&out[oj + lane + 64], p2.x);
    __stcs(&out[OUT_PER + oj + lane],      (p0.y > 0.0f) ? p0.y : 1.0f);
    __stcs(&out[OUT_PER + oj + lane + 32], (p1.y > 0.0f) ? p1.y : 1.0f);
    __stcs(&out[OUT_PER + oj + lane + 64], (p2.y > 0.0f) ? p2.y : 1.0f);
    if (lane < 24) {
        __stcs(&out[oj + lane + 96],           p3.x);
        __stcs(&out[OUT_PER + oj + lane + 96], (p3.y > 0.0f) ? p3.y : 1.0f);
    }
}

// ---------------------------------------------------------------------------
extern "C" void kernel_launch(void* const* d_in, const int* in_sizes, int n_in,
                              void* d_out, int out_size)
{
    const float* vol = (const float*)d_in[0];
    const float* trf = (const float*)d_in[1];
    float* out = (float*)d_out;

    splat_kernel<<<BB * 9 * 8 * 4, 256>>>(vol, trf);
    finalize_kernel<<<(HWSZ * BB) / 8, 256>>>(out);

    // Restore the all-zero invariant for the next replay; also leaves the
    // accumulator zeroed and warm in L2 for the next splat.
    void* acc_ptr = nullptr;
    cudaGetSymbolAddress(&acc_ptr, g_acc);
    cudaMemsetAsync(acc_ptr, 0, sizeof(float) * 2 * VOXELS, 0);
}

// round 16
// speedup vs baseline: 1.2410x; 1.2410x over previous
#include <cuda_runtime.h>
#include <cstdint>

// ---- problem constants (match reference) ----
#define BB 4
#define HH 128
#define WW 128
#define SS 72
#define SPS 24          // slices per stack
#define ZS 120          // z_scale
#define ZV 122          // padded depth
#define ST_RATIO 5.0f

#define VOXELS (BB * HH * WW * ZV)      // 7,995,392
#define PIXELS (BB * HH * WW * SS)      // 4,718,592
#define OUT_PER (BB * HH * WW * ZS)     // 7,864,320
#define HWSZ   (HH * WW)                // 16384

#define CHAIN 16                         // h-pixels per thread (u-chain length)

// Interleaved scratch: [2*lin]=N, [2*lin+1]=D. 64 MB, L2-resident.
// Zero-initialized at module load; finalize re-zeroes every pair it owns
// (including the z pads) at the end of each execution, restoring the
// all-zero invariant for the next run/replay — no memset needed.
__device__ __align__(16) float g_acc[2 * VOXELS];

__device__ __forceinline__ void red_add_v2(float* p, float a, float b) {
    asm volatile("red.global.add.v2.f32 [%0], {%1, %2};"
                 :: "l"(p), "f"(a), "f"(b) : "memory");
}

__device__ __forceinline__ void red_add_v4(float* p, float a, float b,
                                           float c, float d) {
    asm volatile("red.global.add.v4.f32 [%0], {%1, %2, %3, %4};"
                 :: "l"(p), "f"(a), "f"(b), "f"(c), "f"(d) : "memory");
}

// Per-axis corner terms: clipped address contributions + masked weights.
struct Axis { int t0, t1; float f0, f1; };

__device__ __forceinline__ Axis axis_eval(float q, int E, int St) {
    float qf = floorf(q);
    int q0 = (int)qf;
    float fr = q - qf;
    int i0 = min(max(q0, 0), E - 1);
    int i1 = min(max(q0 + 1, 0), E - 1);
    Axis a;
    a.t0 = i0 * St;
    a.t1 = i1 * St;
    a.f0 = (q0 >= 0 && q0 < E)      ? (1.0f - fr) : 0.0f;
    a.f1 = (q0 >= -1 && q0 < E - 1) ? fr          : 0.0f;
    return a;
}

// ---------------------------------------------------------------------------
// Splat (exact R11 structure — measured best; reorientation and lane-pair
// fusion both REGRESSED due to loss of warp-level red-address locality).
// Warp = 32 lanes spanning w. Each thread serially chains CHAIN h-pixels,
// carrying the u1-row in registers and merging on exact address equality.
// Axis roles per orientation:
//   axi: u=x(h, stride W*ZV)  v=y(w, stride ZV)  c=z(stride 1)
//   cor: u=x(h, stride W*ZV)  v=z(w, stride 1)   c=y(stride ZV)
//   sag: u=y(h, stride ZV)    v=z(w, stride 1)   c=x(stride W*ZV)
// axi's two c-corners are z-adjacent -> lane-uniform v4 fusion of the c pair.
// Grid = B * 9(sc) * 8(hc) * 4(wc) = 1152 blocks of 256.
// ---------------------------------------------------------------------------
__global__ __launch_bounds__(256) void splat_kernel(
    const float* __restrict__ vol,    // (B,H,W,S,1)
    const float* __restrict__ trf)    // (B,S,3,4)
{
    __shared__ float sv[CHAIN * 32 * 9];  // [ (h_local*32 + w_local)*9 + s_local ]

    int tid  = threadIdx.x;
    int lane = tid & 31;
    int wid  = tid >> 5;
    int blk  = blockIdx.x;

    int wc = blk & 3;
    int tt = blk >> 2;
    int hc = tt & 7;   tt >>= 3;       // 128/CHAIN = 8 h-chunks
    int sc = tt % 9;
    int b  = tt / 9;

    int h0 = hc * CHAIN, w0 = wc * 32;
    int s  = sc * 8 + wid;            // warp-uniform

    // Stage vol[b, h0..h0+CHAIN-1, w0..w0+31, sc*8..+7] into smem (coalesced,
    // sector-efficient; pad-9 rows for conflict-free readback).
    {
        const float* base = vol + (((size_t)(b * HH + h0) * WW + w0) * SS + sc * 8);
        #pragma unroll
        for (int it = 0; it < CHAIN; it++) {
            int idx = it * 256 + tid;
            int hh = idx >> 8;
            int wl = (idx >> 3) & 31;
            int sl = idx & 7;
            sv[(hh * 32 + wl) * 9 + sl] = base[((size_t)hh * WW + wl) * SS + sl];
        }
    }
    __syncthreads();

    const float* Ap = trf + (size_t)(b * SS + s) * 12;
    float A00 = Ap[0] + 1.0f, A01 = Ap[1],        A02 = Ap[2],         A03 = Ap[3];
    float A10 = Ap[4],        A11 = Ap[5] + 1.0f, A12 = Ap[6],         A13 = Ap[7];
    float A20 = Ap[8],        A21 = Ap[9],        A22 = Ap[10] + 1.0f, A23 = Ap[11];

    int o = s / SPS;                  // warp-uniform orientation
    float tc = (float)(s % SPS) * ST_RATIO;
    int w = w0 + lane;
    int bb = b * HH * WW * ZV;

    // carry per c-corner: pixel p's u1-row awaiting merge with p+1's u0-row
    int   cLoA[2] = { -1, -1 };
    float cLoN[2], cLoD[2];
    int   cHiA[2];
    float cHiN[2], cHiD[2];
    bool  cHiS[2] = { false, false };

    for (int p = 0; p < CHAIN; p++) {
        int h = h0 + p;
        float v = sv[(p * 32 + lane) * 9 + wid];   // conflict-free (stride 9)

        float bx, by, bz;
        if (o == 0)      { bx = (float)h; by = (float)w; bz = tc; }
        else if (o == 1) { bx = (float)h; by = tc;       bz = (float)w; }
        else             { bx = tc;       by = (float)h; bz = (float)w; }

        float x = A00 * bx + A01 * by + A02 * bz + A03;
        float y = A10 * bx + A11 * by + A12 * bz + A13;
        float z = A20 * bx + A21 * by + A22 * bz + A23 + 1.0f;

        Axis U, V, C;
        if (o == 0) {
            U = axis_eval(x, HH, WW * ZV);
            V = axis_eval(y, WW, ZV);
            C = axis_eval(z, ZV, 1);
        } else if (o == 1) {
            U = axis_eval(x, HH, WW * ZV);
            V = axis_eval(z, ZV, 1);
            C = axis_eval(y, WW, ZV);
        } else {
            U = axis_eval(y, WW, ZV);
            V = axis_eval(z, ZV, 1);
            C = axis_eval(x, HH, WW * ZV);
        }

        // lo-row emission candidates per c (filled below, emitted after)
        int   eL[2];
        float eN[2], eD[2];

        #pragma unroll
        for (int c = 0; c < 2; c++) {
            int   ct = c ? C.t1 : C.t0;
            float fc = c ? C.f1 : C.f0;

            int   rL[2], rH[2];
            float rAccN[2], rAccD[2], rHiN[2], rHiD[2];
            bool  rS[2];

            // v-merge along the 32-lane w run, for both u rows
            #pragma unroll
            for (int r = 0; r < 2; r++) {
                int   ut = r ? U.t1 : U.t0;
                float fu = r ? U.f1 : U.f0;
                int L  = bb + ut + V.t0 + ct;
                int Hh = bb + ut + V.t1 + ct;
                float wlo = fu * V.f0 * fc;
                float whi = fu * V.f1 * fc;
                float NhiV = whi * v;

                float nbN = __shfl_up_sync(0xffffffffu, NhiV, 1);
                float nbD = __shfl_up_sync(0xffffffffu, whi, 1);
                int   nbH = __shfl_up_sync(0xffffffffu, Hh, 1);
                bool mrg = (lane > 0) && (nbH == L);
                unsigned bal = __ballot_sync(0xffffffffu, mrg);
                bool absorbed = (bal & (2u << lane)) != 0u;  // lane31 -> false

                rL[r]    = L;
                rAccN[r] = wlo * v + (mrg ? nbN : 0.0f);
                rAccD[r] = wlo     + (mrg ? nbD : 0.0f);
                rH[r]    = Hh;
                rHiN[r]  = NhiV;
                rHiD[r]  = whi;
                rS[r]    = !absorbed;
            }

            // u-chain: absorb previous pixel's u1-row (carry) into this u0-row
            if (cLoA[c] >= 0) {
                if (cLoA[c] == rL[0]) {
                    rAccN[0] += cLoN[c];
                    rAccD[0] += cLoD[c];
                } else {
                    red_add_v2(&g_acc[2 * cLoA[c]], cLoN[c], cLoD[c]);
                }
                if (cHiS[c]) {
                    if (rS[0] && cHiA[c] == rH[0]) {
                        rHiN[0] += cHiN[c];
                        rHiD[0] += cHiD[c];
                    } else {
                        red_add_v2(&g_acc[2 * cHiA[c]], cHiN[c], cHiD[c]);
                    }
                }
            }

            // record u0-row lo emission; emit surviving u0-row hi now (rare)
            eL[c] = rL[0]; eN[c] = rAccN[0]; eD[c] = rAccD[0];
            if (rS[0])
                red_add_v2(&g_acc[2 * rH[0]], rHiN[0], rHiD[0]);

            // u1-row becomes the new carry
            cLoA[c] = rL[1]; cLoN[c] = rAccN[1]; cLoD[c] = rAccD[1];
            cHiA[c] = rH[1]; cHiN[c] = rHiN[1]; cHiD[c] = rHiD[1];
            cHiS[c] = rS[1];
        }

        // emit the two lo-rows; axi fuses adjacent c-pairs into one v4 red
        if (o == 0) {
            bool fuse = (eL[1] == eL[0] + 1) && ((eL[0] & 1) == 0);
            if (fuse) {
                red_add_v4(&g_acc[2 * eL[0]], eN[0], eD[0], eN[1], eD[1]);
            } else {
                red_add_v2(&g_acc[2 * eL[0]], eN[0], eD[0]);
                red_add_v2(&g_acc[2 * eL[1]], eN[1], eD[1]);
            }
        } else {
            red_add_v2(&g_acc[2 * eL[0]], eN[0], eD[0]);
            red_add_v2(&g_acc[2 * eL[1]], eN[1], eD[1]);
        }
    }

    // flush remaining carries
    #pragma unroll
    for (int c = 0; c < 2; c++) {
        if (cLoA[c] >= 0) {
            red_add_v2(&g_acc[2 * cLoA[c]], cLoN[c], cLoD[c]);
            if (cHiS[c])
                red_add_v2(&g_acc[2 * cHiA[c]], cHiN[c], cHiD[c]);
        }
    }
}

// ---------------------------------------------------------------------------
// Finalize + rezero: crop z[1:1+ZS], split interleaved N/D, where(D<=0,1,D),
// then zero this column's ENTIRE accumulator range (offsets 0..121, incl.
// pads) with coalesced float2 stores — replaces the tail memset.
// One warp per (b,h,w) column; strided passes of 32 z (last predicated).
// Hazard: lane l's zero at offset k can alias lane l-1's read at offset k —
// out-stores consume the loads first, then __syncwarp(), then zero.
// Zero-stores use default caching (lines stay L2-resident for the next
// splat's reds); out-stores stream (__stcs).
// Grid = HWSZ*BB/8 = 8192 blocks of 256 (8 warps = 8 columns per block).
// ---------------------------------------------------------------------------
__global__ __launch_bounds__(256) void finalize_kernel(float* __restrict__ out)
{
    int lane = threadIdx.x & 31;
    int col  = blockIdx.x * 8 + (threadIdx.x >> 5);   // global hwb column

    float2* acc = reinterpret_cast<float2*>(g_acc);
    int base = col * ZV;
    int lin  = base + 1;
    int oj   = col * ZS;

    float2 p0 = __ldcs(&acc[lin + lane]);
    float2 p1 = __ldcs(&acc[lin + lane + 32]);
    float2 p2 = __ldcs(&acc[lin + lane + 64]);
    float2 p3 = (lane < 24) ? __ldcs(&acc[lin + lane + 96]) : make_float2(0.f, 0.f);

    __stcs(&out[oj + lane],      p0.x);
    __stcs(&out[oj + lane + 32], p1.x);
    __stcs(&out[oj + lane + 64], p2.x);
    __stcs(&out[OUT_PER + oj + lane],      (p0.y > 0.0f) ? p0.y : 1.0f);
    __stcs(&out[OUT_PER + oj + lane + 32], (p1.y > 0.0f) ? p1.y : 1.0f);
    __stcs(&out[OUT_PER + oj + lane + 64], (p2.y > 0.0f) ? p2.y : 1.0f);
    if (lane < 24) {
        __stcs(&out[oj + lane + 96],           p3.x);
        __stcs(&out[OUT_PER + oj + lane + 96], (p3.y > 0.0f) ? p3.y : 1.0f);
    }

    // All lanes' loads are complete (consumed by the stores above); now it is
    // safe to overwrite neighboring lanes' read addresses.
    __syncwarp();

    const float2 zz = make_float2(0.0f, 0.0f);
    acc[base + lane]      = zz;
    acc[base + lane + 32] = zz;
    acc[base + lane + 64] = zz;
    if (lane < 26)                         // offsets 96..121 (incl. pad 121)
        acc[base + lane + 96] = zz;
}

// ---------------------------------------------------------------------------
extern "C" void kernel_launch(void* const* d_in, const int* in_sizes, int n_in,
                              void* d_out, int out_size)
{
    const float* vol = (const float*)d_in[0];
    const float* trf = (const float*)d_in[1];
    float* out = (float*)d_out;

    splat_kernel<<<BB * 9 * (HH / CHAIN) * 4, 256>>>(vol, trf);
    finalize_kernel<<<(HWSZ * BB) / 8, 256>>>(out);
}

// round 17
// speedup vs baseline: 1.2484x; 1.0060x over previous
#include <cuda_runtime.h>
#include <cstdint>

// ---- problem constants (match reference) ----
#define BB 4
#define HH 128
#define WW 128
#define SS 72
#define SPS 24          // slices per stack
#define ZS 120          // z_scale
#define ZV 122          // padded depth
#define ST_RATIO 5.0f

#define VOXELS (BB * HH * WW * ZV)      // 7,995,392
#define PIXELS (BB * HH * WW * SS)      // 4,718,592
#define OUT_PER (BB * HH * WW * ZS)     // 7,864,320
#define HWSZ   (HH * WW)                // 16384

#define CHAIN 16                         // h-pixels per thread (u-chain length)

// Interleaved scratch: [2*lin]=N, [2*lin+1]=D. 64 MB, L2-resident.
// Zero-initialized at module load; finalize re-zeroes every pair it owns
// (including the z pads) at the end of each execution, restoring the
// all-zero invariant for the next run/replay — no memset needed (and the
// plain dirty zero stores leave the lines warm in L2 for the next splat,
// which measured FASTER than a tail cudaMemsetAsync).
__device__ __align__(16) float g_acc[2 * VOXELS];

__device__ __forceinline__ void red_add_v2(float* p, float a, float b) {
    asm volatile("red.global.add.v2.f32 [%0], {%1, %2};"
                 :: "l"(p), "f"(a), "f"(b) : "memory");
}

__device__ __forceinline__ void red_add_v4(float* p, float a, float b,
                                           float c, float d) {
    asm volatile("red.global.add.v4.f32 [%0], {%1, %2, %3, %4};"
                 :: "l"(p), "f"(a), "f"(b), "f"(c), "f"(d) : "memory");
}

// Per-axis corner terms: clipped address contributions + masked weights.
struct Axis { int t0, t1; float f0, f1; };

__device__ __forceinline__ Axis axis_eval(float q, int E, int St) {
    float qf = floorf(q);
    int q0 = (int)qf;
    float fr = q - qf;
    int i0 = min(max(q0, 0), E - 1);
    int i1 = min(max(q0 + 1, 0), E - 1);
    Axis a;
    a.t0 = i0 * St;
    a.t1 = i1 * St;
    a.f0 = (q0 >= 0 && q0 < E)      ? (1.0f - fr) : 0.0f;
    a.f1 = (q0 >= -1 && q0 < E - 1) ? fr          : 0.0f;
    return a;
}

// ---------------------------------------------------------------------------
// Splat (exact R11 structure — measured best; reorientation and lane-pair
// fusion both REGRESSED due to loss of warp-level red-address locality).
// Warp = 32 lanes spanning w. Each thread serially chains CHAIN h-pixels,
// carrying the u1-row in registers and merging on exact address equality.
// Axis roles per orientation:
//   axi: u=x(h, stride W*ZV)  v=y(w, stride ZV)  c=z(stride 1)
//   cor: u=x(h, stride W*ZV)  v=z(w, stride 1)   c=y(stride ZV)
//   sag: u=y(h, stride ZV)    v=z(w, stride 1)   c=x(stride W*ZV)
// axi's two c-corners are z-adjacent -> lane-uniform v4 fusion of the c pair.
// Grid = B * 9(sc) * 8(hc) * 4(wc) = 1152 blocks of 256.
// ---------------------------------------------------------------------------
__global__ __launch_bounds__(256) void splat_kernel(
    const float* __restrict__ vol,    // (B,H,W,S,1)
    const float* __restrict__ trf)    // (B,S,3,4)
{
    __shared__ float sv[CHAIN * 32 * 9];  // [ (h_local*32 + w_local)*9 + s_local ]

    int tid  = threadIdx.x;
    int lane = tid & 31;
    int wid  = tid >> 5;
    int blk  = blockIdx.x;

    int wc = blk & 3;
    int tt = blk >> 2;
    int hc = tt & 7;   tt >>= 3;       // 128/CHAIN = 8 h-chunks
    int sc = tt % 9;
    int b  = tt / 9;

    int h0 = hc * CHAIN, w0 = wc * 32;
    int s  = sc * 8 + wid;            // warp-uniform

    // Stage vol[b, h0..h0+CHAIN-1, w0..w0+31, sc*8..+7] into smem (coalesced,
    // sector-efficient; pad-9 rows for conflict-free readback).
    {
        const float* base = vol + (((size_t)(b * HH + h0) * WW + w0) * SS + sc * 8);
        #pragma unroll
        for (int it = 0; it < CHAIN; it++) {
            int idx = it * 256 + tid;
            int hh = idx >> 8;
            int wl = (idx >> 3) & 31;
            int sl = idx & 7;
            sv[(hh * 32 + wl) * 9 + sl] = base[((size_t)hh * WW + wl) * SS + sl];
        }
    }
    __syncthreads();

    const float* Ap = trf + (size_t)(b * SS + s) * 12;
    float A00 = Ap[0] + 1.0f, A01 = Ap[1],        A02 = Ap[2],         A03 = Ap[3];
    float A10 = Ap[4],        A11 = Ap[5] + 1.0f, A12 = Ap[6],         A13 = Ap[7];
    float A20 = Ap[8],        A21 = Ap[9],        A22 = Ap[10] + 1.0f, A23 = Ap[11];

    int o = s / SPS;                  // warp-uniform orientation
    float tc = (float)(s % SPS) * ST_RATIO;
    int w = w0 + lane;
    int bb = b * HH * WW * ZV;

    // carry per c-corner: pixel p's u1-row awaiting merge with p+1's u0-row
    int   cLoA[2] = { -1, -1 };
    float cLoN[2], cLoD[2];
    int   cHiA[2];
    float cHiN[2], cHiD[2];
    bool  cHiS[2] = { false, false };

    for (int p = 0; p < CHAIN; p++) {
        int h = h0 + p;
        float v = sv[(p * 32 + lane) * 9 + wid];   // conflict-free (stride 9)

        float bx, by, bz;
        if (o == 0)      { bx = (float)h; by = (float)w; bz = tc; }
        else if (o == 1) { bx = (float)h; by = tc;       bz = (float)w; }
        else             { bx = tc;       by = (float)h; bz = (float)w; }

        float x = A00 * bx + A01 * by + A02 * bz + A03;
        float y = A10 * bx + A11 * by + A12 * bz + A13;
        float z = A20 * bx + A21 * by + A22 * bz + A23 + 1.0f;

        Axis U, V, C;
        if (o == 0) {
            U = axis_eval(x, HH, WW * ZV);
            V = axis_eval(y, WW, ZV);
            C = axis_eval(z, ZV, 1);
        } else if (o == 1) {
            U = axis_eval(x, HH, WW * ZV);
            V = axis_eval(z, ZV, 1);
            C = axis_eval(y, WW, ZV);
        } else {
            U = axis_eval(y, WW, ZV);
            V = axis_eval(z, ZV, 1);
            C = axis_eval(x, HH, WW * ZV);
        }

        // lo-row emission candidates per c (filled below, emitted after)
        int   eL[2];
        float eN[2], eD[2];

        #pragma unroll
        for (int c = 0; c < 2; c++) {
            int   ct = c ? C.t1 : C.t0;
            float fc = c ? C.f1 : C.f0;

            int   rL[2], rH[2];
            float rAccN[2], rAccD[2], rHiN[2], rHiD[2];
            bool  rS[2];

            // v-merge along the 32-lane w run, for both u rows
            #pragma unroll
            for (int r = 0; r < 2; r++) {
                int   ut = r ? U.t1 : U.t0;
                float fu = r ? U.f1 : U.f0;
                int L  = bb + ut + V.t0 + ct;
                int Hh = bb + ut + V.t1 + ct;
                float wlo = fu * V.f0 * fc;
                float whi = fu * V.f1 * fc;
                float NhiV = whi * v;

                float nbN = __shfl_up_sync(0xffffffffu, NhiV, 1);
                float nbD = __shfl_up_sync(0xffffffffu, whi, 1);
                int   nbH = __shfl_up_sync(0xffffffffu, Hh, 1);
                bool mrg = (lane > 0) && (nbH == L);
                unsigned bal = __ballot_sync(0xffffffffu, mrg);
                bool absorbed = (bal & (2u << lane)) != 0u;  // lane31 -> false

                rL[r]    = L;
                rAccN[r] = wlo * v + (mrg ? nbN : 0.0f);
                rAccD[r] = wlo     + (mrg ? nbD : 0.0f);
                rH[r]    = Hh;
                rHiN[r]  = NhiV;
                rHiD[r]  = whi;
                rS[r]    = !absorbed;
            }

            // u-chain: absorb previous pixel's u1-row (carry) into this u0-row
            if (cLoA[c] >= 0) {
                if (cLoA[c] == rL[0]) {
                    rAccN[0] += cLoN[c];
                    rAccD[0] += cLoD[c];
                } else {
                    red_add_v2(&g_acc[2 * cLoA[c]], cLoN[c], cLoD[c]);
                }
                if (cHiS[c]) {
                    if (rS[0] && cHiA[c] == rH[0]) {
                        rHiN[0] += cHiN[c];
                        rHiD[0] += cHiD[c];
                    } else {
                        red_add_v2(&g_acc[2 * cHiA[c]], cHiN[c], cHiD[c]);
                    }
                }
            }

            // record u0-row lo emission; emit surviving u0-row hi now (rare)
            eL[c] = rL[0]; eN[c] = rAccN[0]; eD[c] = rAccD[0];
            if (rS[0])
                red_add_v2(&g_acc[2 * rH[0]], rHiN[0], rHiD[0]);

            // u1-row becomes the new carry
            cLoA[c] = rL[1]; cLoN[c] = rAccN[1]; cLoD[c] = rAccD[1];
            cHiA[c] = rH[1]; cHiN[c] = rHiN[1]; cHiD[c] = rHiD[1];
            cHiS[c] = rS[1];
        }

        // emit the two lo-rows; axi fuses adjacent c-pairs into one v4 red
        if (o == 0) {
            bool fuse = (eL[1] == eL[0] + 1) && ((eL[0] & 1) == 0);
            if (fuse) {
                red_add_v4(&g_acc[2 * eL[0]], eN[0], eD[0], eN[1], eD[1]);
            } else {
                red_add_v2(&g_acc[2 * eL[0]], eN[0], eD[0]);
                red_add_v2(&g_acc[2 * eL[1]], eN[1], eD[1]);
            }
        } else {
            red_add_v2(&g_acc[2 * eL[0]], eN[0], eD[0]);
            red_add_v2(&g_acc[2 * eL[1]], eN[1], eD[1]);
        }
    }

    // flush remaining carries
    #pragma unroll
    for (int c = 0; c < 2; c++) {
        if (cLoA[c] >= 0) {
            red_add_v2(&g_acc[2 * cLoA[c]], cLoN[c], cLoD[c]);
            if (cHiS[c])
                red_add_v2(&g_acc[2 * cHiA[c]], cHiN[c], cHiD[c]);
        }
    }
}

// ---------------------------------------------------------------------------
// Finalize + rezero: crop z[1:1+ZS], split interleaved N/D, where(D<=0,1,D),
// then zero this column's ENTIRE accumulator range (offsets 0..121, incl.
// pads) — replaces the memset. One warp per (b,h,w) column.
// Wide version: lanes 0..29 each own 4 consecutive z values -> one float4
// store per output block per lane; zeroing uses aligned float4 stores
// (column = 244 floats = 61 float4s, 16B-aligned since col*976 % 16 == 0).
// Hazard: zero stores may alias other lanes' read addresses; every lane's
// loads are consumed by its out-stores before __syncwarp(), after which
// zeroing is safe. Out uses __stcs (streaming); zeroes use default caching
// (stay L2-resident for the next splat's reds).
// Grid = HWSZ*BB/8 = 8192 blocks of 256 (8 warps = 8 columns per block).
// ---------------------------------------------------------------------------
__global__ __launch_bounds__(256) void finalize_kernel(float* __restrict__ out)
{
    int lane = threadIdx.x & 31;
    int col  = blockIdx.x * 8 + (threadIdx.x >> 5);   // global hwb column

    float2* acc = reinterpret_cast<float2*>(g_acc);
    int base = col * ZV;

    if (lane < 30) {
        int l0 = base + 1 + lane * 4;
        float2 q0 = __ldcs(&acc[l0]);
        float2 q1 = __ldcs(&acc[l0 + 1]);
        float2 q2 = __ldcs(&acc[l0 + 2]);
        float2 q3 = __ldcs(&acc[l0 + 3]);

        int oj = col * ZS + lane * 4;
        float4 nv = make_float4(q0.x, q1.x, q2.x, q3.x);
        float4 dv = make_float4(q0.y > 0.0f ? q0.y : 1.0f,
                                q1.y > 0.0f ? q1.y : 1.0f,
                                q2.y > 0.0f ? q2.y : 1.0f,
                                q3.y > 0.0f ? q3.y : 1.0f);
        __stcs(reinterpret_cast<float4*>(&out[oj]),           nv);
        __stcs(reinterpret_cast<float4*>(&out[OUT_PER + oj]), dv);
    }

    // All lanes' loads are complete (consumed by the stores above); now it is
    // safe to overwrite neighboring lanes' read addresses.
    __syncwarp();

    float4* az = reinterpret_cast<float4*>(g_acc + (size_t)col * (2 * ZV));
    const float4 z4 = make_float4(0.0f, 0.0f, 0.0f, 0.0f);
    az[lane] = z4;                 // float4s 0..31
    if (lane < 29)
        az[32 + lane] = z4;        // float4s 32..60 (244 floats total)
}

// ---------------------------------------------------------------------------
extern "C" void kernel_launch(void* const* d_in, const int* in_sizes, int n_in,
                              void* d_out, int out_size)
{
    const float* vol = (const float*)d_in[0];
    const float* trf = (const float*)d_in[1];
    float* out = (float*)d_out;

    splat_kernel<<<BB * 9 * (HH / CHAIN) * 4, 256>>>(vol, trf);
    finalize_kernel<<<(HWSZ * BB) / 8, 256>>>(out);
}